// round 7
// baseline (speedup 1.0000x reference)
#include <cuda_runtime.h>
#include <cuda_bf16.h>
#include <math.h>

#define T 1024
#define H 2048
#define I_DIM 1024
#define E 32

#define BM 64
#define BK 32
#define PITCH 40           // bf16 elems per A smem row (32 + 8 pad)
#define FPITCH 40          // fp32 elems per B smem row (32 + 8 pad)
#define STAGE_BYTES 30720  // Ah 5120 | Al 5120 | B0 10240..20480 | B1 20480..30720

// Scratch (__device__ globals; no allocations allowed)
__device__ int   g_count[E];
__device__ int   g_list[E * 2 * T];
__device__ float g_pairw[T * 2];
__device__ __align__(16) unsigned g_xh[T * H / 2];        // x split hi (bf16x2)
__device__ __align__(16) unsigned g_xl[T * H / 2];        // x split lo
__device__ __align__(16) unsigned g_hh[T * 2 * I_DIM / 2]; // h split hi
__device__ __align__(16) unsigned g_hl[T * 2 * I_DIM / 2]; // h split lo

// ---------------------------------------------------------------------------
__global__ void zero_kernel(float* __restrict__ out) {
    int i = blockIdx.x * blockDim.x + threadIdx.x;
    if (i < T * H) out[i] = 0.0f;
    if (i < E) g_count[i] = 0;
}

// split float2 -> bf16x2 hi + bf16x2 lo (lo = rn(v - hi))
__device__ __forceinline__ void split2(float2 v, unsigned &hi, unsigned &lo) {
    __nv_bfloat162 hb = __float22bfloat162_rn(v);
    float2 hf = __bfloat1622float2(hb);
    __nv_bfloat162 lb = __float22bfloat162_rn(make_float2(v.x - hf.x, v.y - hf.y));
    hi = *reinterpret_cast<unsigned*>(&hb);
    lo = *reinterpret_cast<unsigned*>(&lb);
}

__global__ void convert_x_kernel(const float* __restrict__ x) {
    int i = blockIdx.x * blockDim.x + threadIdx.x;   // over T*H/2 float2
    float2 v = ((const float2*)x)[i];
    unsigned h, l;
    split2(v, h, l);
    g_xh[i] = h;
    g_xl[i] = l;
}

// ---------------------------------------------------------------------------
__global__ __launch_bounds__(128) void router_kernel(
    const float* __restrict__ x, const float* __restrict__ gw) {
    int t = blockIdx.x;
    __shared__ float logits[E];
    int warp = threadIdx.x >> 5;
    int lane = threadIdx.x & 31;
    const float4* xt = (const float4*)(x + (size_t)t * H);

    for (int e = warp; e < E; e += 4) {
        const float4* w = (const float4*)(gw + (size_t)e * H);
        float s = 0.0f;
        #pragma unroll 4
        for (int h = lane; h < H / 4; h += 32) {
            float4 a = xt[h];
            float4 b = w[h];
            s += a.x * b.x + a.y * b.y + a.z * b.z + a.w * b.w;
        }
        #pragma unroll
        for (int o = 16; o; o >>= 1) s += __shfl_xor_sync(0xffffffffu, s, o);
        if (lane == 0) logits[e] = s;
    }
    __syncthreads();

    if (threadIdx.x == 0) {
        float b1 = -1e30f, b2 = -1e30f;
        int i1 = 0, i2 = 0;
        #pragma unroll
        for (int e = 0; e < E; e++) {
            float v = logits[e];
            if (v > b1)      { b2 = b1; i2 = i1; b1 = v; i1 = e; }
            else if (v > b2) { b2 = v; i2 = e; }
        }
        float w1 = 1.0f / (1.0f + expf(b2 - b1));
        float w2 = 1.0f - w1;
        g_pairw[t * 2 + 0] = w1;
        g_pairw[t * 2 + 1] = w2;
        int p1 = atomicAdd(&g_count[i1], 1);
        g_list[i1 * 2 * T + p1] = t * 2 + 0;
        int p2 = atomicAdd(&g_count[i2], 1);
        g_list[i2 * 2 * T + p2] = t * 2 + 1;
    }
}

// ---------------------------------------------------------------------------
__device__ __forceinline__ unsigned smem_u32(const void* p) {
    return (unsigned)__cvta_generic_to_shared(p);
}
__device__ __forceinline__ void ldsm_x4(unsigned addr, unsigned (&r)[4]) {
    asm volatile("ldmatrix.sync.aligned.m8n8.x4.shared.b16 {%0,%1,%2,%3}, [%4];\n"
        : "=r"(r[0]), "=r"(r[1]), "=r"(r[2]), "=r"(r[3]) : "r"(addr));
}
__device__ __forceinline__ void mma16816(float (&c)[4], const unsigned (&a)[4],
                                         unsigned b0, unsigned b1) {
    asm volatile(
        "mma.sync.aligned.m16n8k16.row.col.f32.bf16.bf16.f32 "
        "{%0,%1,%2,%3}, {%4,%5,%6,%7}, {%8,%9}, {%0,%1,%2,%3};\n"
        : "+f"(c[0]), "+f"(c[1]), "+f"(c[2]), "+f"(c[3])
        : "r"(a[0]), "r"(a[1]), "r"(a[2]), "r"(a[3]), "r"(b0), "r"(b1));
}
__device__ __forceinline__ void cp_async16(unsigned dst, const void* src) {
    asm volatile("cp.async.cg.shared.global [%0], [%1], 16;\n" :: "r"(dst), "l"(src));
}
#define CP_COMMIT() asm volatile("cp.async.commit_group;\n" ::: "memory")
#define CP_WAIT(n)  asm volatile("cp.async.wait_group %0;\n" :: "n"(n) : "memory")

// ---------------------------------------------------------------------------
// Gate+Up: M=64 slots x N=64 i-cols, K=H. A: bf16 hi/lo via cp.async+ldmatrix.
// B (Wg,Wu): fp32 via cp.async; fragments loaded as float2, split in regs.
__global__ __launch_bounds__(256) void gateup_kernel(
    const float* __restrict__ Wg, const float* __restrict__ Wu) {
    extern __shared__ char dynsmem[];
    int e = blockIdx.z;
    int cnt = g_count[e];
    int slot0 = blockIdx.x * BM;
    if (slot0 >= cnt) return;
    int i0 = blockIdx.y * 64;

    __shared__ int spair[BM];
    int tid = threadIdx.x;
    if (tid < BM) {
        int s = slot0 + tid;
        spair[tid] = (s < cnt) ? g_list[e * 2 * T + s] : g_list[e * 2 * T];
    }
    __syncthreads();

    unsigned sbase = smem_u32(dynsmem);

    // cp.async mapping: A row = tid>>2 (64 rows), chunk = tid&3 (4x16B = 64B row)
    int arow = tid >> 2;
    int achk = tid & 3;
    int token = spair[arow] >> 1;
    const char* srcAh = (const char*)g_xh + (size_t)token * H * 2 + achk * 16;
    const char* srcAl = (const char*)g_xl + (size_t)token * H * 2 + achk * 16;
    unsigned dstA = arow * (PITCH * 2) + achk * 16;
    // B rows = tid>>2, chunks achk*16 and achk*16+64 (8x16B = 128B row)
    const char* srcG = (const char*)(Wg + ((size_t)e * I_DIM + i0 + arow) * H) + achk * 16;
    const char* srcU = (const char*)(Wu + ((size_t)e * I_DIM + i0 + arow) * H) + achk * 16;
    unsigned dstB = arow * (FPITCH * 4) + achk * 16;

    int warp = tid >> 5, lane = tid & 31;
    int wm = warp >> 2;   // 0..1
    int wn = warp & 3;    // 0..3, 16 cols each

    unsigned aoff0 = ((wm * 32 + (lane & 15)) * PITCH + (lane >> 4) * 8) * 2;
    unsigned aoff1 = aoff0 + 16 * PITCH * 2;
    // B fragment float index: row = wn*16 + (lane>>2), col = 2*(lane&3)
    int bidx = (wn * 16 + (lane >> 2)) * FPITCH + 2 * (lane & 3);

    float cg[2][2][4] = {};
    float cu[2][2][4] = {};

    // prologue: stage 0
    cp_async16(sbase + dstA, srcAh);
    cp_async16(sbase + 5120 + dstA, srcAl);
    cp_async16(sbase + 10240 + dstB, srcG);
    cp_async16(sbase + 10240 + dstB + 64, srcG + 64);
    cp_async16(sbase + 20480 + dstB, srcU);
    cp_async16(sbase + 20480 + dstB + 64, srcU + 64);
    CP_COMMIT();

    const int NIT = H / BK;   // 64
    for (int it = 0; it < NIT; ++it) {
        __syncthreads();   // readers of the buffer we are about to overwrite are done
        if (it + 1 < NIT) {
            unsigned sb2 = sbase + ((it + 1) & 1) * STAGE_BYTES;
            size_t kA = (size_t)(it + 1) * BK * 2;   // bytes (bf16)
            size_t kB = (size_t)(it + 1) * BK * 4;   // bytes (fp32)
            cp_async16(sb2 + dstA, srcAh + kA);
            cp_async16(sb2 + 5120 + dstA, srcAl + kA);
            cp_async16(sb2 + 10240 + dstB, srcG + kB);
            cp_async16(sb2 + 10240 + dstB + 64, srcG + kB + 64);
            cp_async16(sb2 + 20480 + dstB, srcU + kB);
            cp_async16(sb2 + 20480 + dstB + 64, srcU + kB + 64);
            CP_COMMIT();
            CP_WAIT(1);
        } else {
            CP_WAIT(0);
        }
        __syncthreads();

        unsigned sb = sbase + (it & 1) * STAGE_BYTES;
        const float* fG = (const float*)(dynsmem + (it & 1) * STAGE_BYTES + 10240);
        const float* fU = (const float*)(dynsmem + (it & 1) * STAGE_BYTES + 20480);

        #pragma unroll
        for (int ks = 0; ks < 2; ks++) {
            unsigned kb = ks * 32;
            unsigned ah0[4], ah1[4], al0[4], al1[4];
            ldsm_x4(sb + aoff0 + kb, ah0);
            ldsm_x4(sb + aoff1 + kb, ah1);
            ldsm_x4(sb + 5120 + aoff0 + kb, al0);
            ldsm_x4(sb + 5120 + aoff1 + kb, al1);

            #pragma unroll
            for (int nt = 0; nt < 2; nt++) {
                int fi = bidx + nt * 8 * FPITCH + ks * 16;
                float2 g0 = *(const float2*)(fG + fi);
                float2 g1 = *(const float2*)(fG + fi + 8);
                float2 u0 = *(const float2*)(fU + fi);
                float2 u1 = *(const float2*)(fU + fi + 8);
                unsigned gh0, gl0, gh1, gl1, uh0, ul0, uh1, ul1;
                split2(g0, gh0, gl0); split2(g1, gh1, gl1);
                split2(u0, uh0, ul0); split2(u1, uh1, ul1);

                mma16816(cg[0][nt], ah0, gh0, gh1);
                mma16816(cg[0][nt], ah0, gl0, gl1);
                mma16816(cg[0][nt], al0, gh0, gh1);
                mma16816(cg[1][nt], ah1, gh0, gh1);
                mma16816(cg[1][nt], ah1, gl0, gl1);
                mma16816(cg[1][nt], al1, gh0, gh1);

                mma16816(cu[0][nt], ah0, uh0, uh1);
                mma16816(cu[0][nt], ah0, ul0, ul1);
                mma16816(cu[0][nt], al0, uh0, uh1);
                mma16816(cu[1][nt], ah1, uh0, uh1);
                mma16816(cu[1][nt], ah1, ul0, ul1);
                mma16816(cu[1][nt], al1, uh0, uh1);
            }
        }
    }

    // epilogue: h = silu(g)*u*w, split to bf16 hi/lo -> g_hh/g_hl
    #pragma unroll
    for (int mi = 0; mi < 2; mi++) {
        #pragma unroll
        for (int half = 0; half < 2; half++) {
            int row = wm * 32 + mi * 16 + (lane >> 2) + half * 8;
            if (slot0 + row < cnt) {
                int pair = spair[row];
                float w = g_pairw[pair];
                #pragma unroll
                for (int ni = 0; ni < 2; ni++) {
                    int col = i0 + wn * 16 + ni * 8 + ((lane & 3) << 1);
                    float g0 = cg[mi][ni][half * 2 + 0];
                    float g1 = cg[mi][ni][half * 2 + 1];
                    float u0 = cu[mi][ni][half * 2 + 0];
                    float u1 = cu[mi][ni][half * 2 + 1];
                    float h0 = g0 / (1.0f + expf(-g0)) * u0 * w;
                    float h1 = g1 / (1.0f + expf(-g1)) * u1 * w;
                    unsigned hv, lv;
                    split2(make_float2(h0, h1), hv, lv);
                    size_t idx = ((size_t)pair * I_DIM + col) >> 1;
                    g_hh[idx] = hv;
                    g_hl[idx] = lv;
                }
            }
        }
    }
}

// ---------------------------------------------------------------------------
// Down: M=64 slots x N=128 h-cols, K=I. A: bf16 hi/lo (g_hh/g_hl). B: Wd fp32.
__global__ __launch_bounds__(256) void down_kernel(
    const float* __restrict__ Wd, float* __restrict__ out) {
    extern __shared__ char dynsmem[];
    int e = blockIdx.z;
    int cnt = g_count[e];
    int slot0 = blockIdx.x * BM;
    if (slot0 >= cnt) return;
    int h0 = blockIdx.y * 128;

    __shared__ int spair[BM];
    int tid = threadIdx.x;
    if (tid < BM) {
        int s = slot0 + tid;
        spair[tid] = (s < cnt) ? g_list[e * 2 * T + s] : g_list[e * 2 * T];
    }
    __syncthreads();

    unsigned sbase = smem_u32(dynsmem);

    int arow = tid >> 2;
    int achk = tid & 3;
    int pr = spair[arow];
    const char* srcAh = (const char*)g_hh + (size_t)pr * I_DIM * 2 + achk * 16;
    const char* srcAl = (const char*)g_hl + (size_t)pr * I_DIM * 2 + achk * 16;
    unsigned dstA = arow * (PITCH * 2) + achk * 16;
    // B: 128 rows x 128B; row = tid>>1, 4 chunks at (tid&1)*64 + j*16
    int brow = tid >> 1;
    int bj = (tid & 1) * 64;
    const char* srcB = (const char*)(Wd + ((size_t)e * H + h0 + brow) * I_DIM) + bj;
    unsigned dstB = brow * (FPITCH * 4) + bj;

    int warp = tid >> 5, lane = tid & 31;
    int wm = warp >> 2;   // 0..1
    int wn = warp & 3;    // 0..3, 32 cols each

    unsigned aoff0 = ((wm * 32 + (lane & 15)) * PITCH + (lane >> 4) * 8) * 2;
    unsigned aoff1 = aoff0 + 16 * PITCH * 2;
    int bidx = (wn * 32 + (lane >> 2)) * FPITCH + 2 * (lane & 3);

    float c[2][4][4] = {};

    // prologue: stage 0
    cp_async16(sbase + dstA, srcAh);
    cp_async16(sbase + 5120 + dstA, srcAl);
    cp_async16(sbase + 10240 + dstB, srcB);
    cp_async16(sbase + 10240 + dstB + 16, srcB + 16);
    cp_async16(sbase + 10240 + dstB + 32, srcB + 32);
    cp_async16(sbase + 10240 + dstB + 48, srcB + 48);
    CP_COMMIT();

    const int NIT = I_DIM / BK;   // 32
    for (int it = 0; it < NIT; ++it) {
        __syncthreads();
        if (it + 1 < NIT) {
            unsigned sb2 = sbase + ((it + 1) & 1) * STAGE_BYTES;
            size_t kA = (size_t)(it + 1) * BK * 2;
            size_t kB = (size_t)(it + 1) * BK * 4;
            cp_async16(sb2 + dstA, srcAh + kA);
            cp_async16(sb2 + 5120 + dstA, srcAl + kA);
            cp_async16(sb2 + 10240 + dstB, srcB + kB);
            cp_async16(sb2 + 10240 + dstB + 16, srcB + kB + 16);
            cp_async16(sb2 + 10240 + dstB + 32, srcB + kB + 32);
            cp_async16(sb2 + 10240 + dstB + 48, srcB + kB + 48);
            CP_COMMIT();
            CP_WAIT(1);
        } else {
            CP_WAIT(0);
        }
        __syncthreads();

        unsigned sb = sbase + (it & 1) * STAGE_BYTES;
        const float* fB = (const float*)(dynsmem + (it & 1) * STAGE_BYTES + 10240);

        #pragma unroll
        for (int ks = 0; ks < 2; ks++) {
            unsigned kb = ks * 32;
            unsigned ah0[4], ah1[4], al0[4], al1[4];
            ldsm_x4(sb + aoff0 + kb, ah0);
            ldsm_x4(sb + aoff1 + kb, ah1);
            ldsm_x4(sb + 5120 + aoff0 + kb, al0);
            ldsm_x4(sb + 5120 + aoff1 + kb, al1);

            #pragma unroll
            for (int nt = 0; nt < 4; nt++) {
                int fi = bidx + nt * 8 * FPITCH + ks * 16;
                float2 b0 = *(const float2*)(fB + fi);
                float2 b1 = *(const float2*)(fB + fi + 8);
                unsigned bh0, bl0, bh1, bl1;
                split2(b0, bh0, bl0); split2(b1, bh1, bl1);

                mma16816(c[0][nt], ah0, bh0, bh1);
                mma16816(c[0][nt], ah0, bl0, bl1);
                mma16816(c[0][nt], al0, bh0, bh1);
                mma16816(c[1][nt], ah1, bh0, bh1);
                mma16816(c[1][nt], ah1, bl0, bl1);
                mma16816(c[1][nt], al1, bh0, bh1);
            }
        }
    }

    // epilogue: scatter-add into out[token][h]
    #pragma unroll
    for (int mi = 0; mi < 2; mi++) {
        #pragma unroll
        for (int half = 0; half < 2; half++) {
            int row = wm * 32 + mi * 16 + (lane >> 2) + half * 8;
            if (slot0 + row < cnt) {
                int token = spair[row] >> 1;
                float* orow = out + (size_t)token * H + h0 + wn * 32;
                #pragma unroll
                for (int ni = 0; ni < 4; ni++) {
                    int col = ni * 8 + ((lane & 3) << 1);
                    atomicAdd(&orow[col],     c[mi][ni][half * 2 + 0]);
                    atomicAdd(&orow[col + 1], c[mi][ni][half * 2 + 1]);
                }
            }
        }
    }
}

// ---------------------------------------------------------------------------
extern "C" void kernel_launch(void* const* d_in, const int* in_sizes, int n_in,
                              void* d_out, int out_size) {
    const float* x  = (const float*)d_in[0];
    const float* gw = (const float*)d_in[1];
    const float* Wg = (const float*)d_in[2];
    const float* Wu = (const float*)d_in[3];
    const float* Wd = (const float*)d_in[4];
    float* out = (float*)d_out;

    cudaFuncSetAttribute(gateup_kernel,
        cudaFuncAttributeMaxDynamicSharedMemorySize, 2 * STAGE_BYTES);
    cudaFuncSetAttribute(down_kernel,
        cudaFuncAttributeMaxDynamicSharedMemorySize, 2 * STAGE_BYTES);

    zero_kernel<<<(T * H + 255) / 256, 256>>>(out);
    convert_x_kernel<<<(T * H / 2) / 256, 256>>>(x);
    router_kernel<<<T, 128>>>(x, gw);
    {
        dim3 grid(T * 2 / BM, I_DIM / 64, E);
        gateup_kernel<<<grid, 256, 2 * STAGE_BYTES>>>(Wg, Wu);
    }
    {
        dim3 grid(T * 2 / BM, H / 128, E);
        down_kernel<<<grid, 256, 2 * STAGE_BYTES>>>(Wd, out);
    }
}